// round 1
// baseline (speedup 1.0000x reference)
#include <cuda_runtime.h>

#define B_    128
#define N_    4096
#define C_    768
#define H_    768
#define NC_   1000
#define TOPK_ 16
#define M_    (B_*TOPK_)   // 2048

// Scratch (static device globals — allocation-free per harness rules)
__device__ float g_xg[M_*C_];     // gathered x_topk [2048][768]  (~6.3 MB)
__device__ float g_score[M_];     // attention pre-softmax scores
__device__ float g_z[B_*C_];      // pooled features [128][768]

__device__ __forceinline__ unsigned long long fma2(unsigned long long a,
                                                   unsigned long long b,
                                                   unsigned long long c) {
    unsigned long long d;
    asm("fma.rn.f32x2 %0, %1, %2, %3;" : "=l"(d) : "l"(a), "l"(b), "l"(c));
    return d;
}

// ---------------------------------------------------------------------------
// Kernel 1: per-batch top-16 of r + gather x rows + zero score buffer
// ---------------------------------------------------------------------------
__global__ __launch_bounds__(256) void topk_gather_kernel(
    const float* __restrict__ x, const float* __restrict__ r)
{
    __shared__ float sr[N_];
    __shared__ float rv[256];
    __shared__ int   ri[256];
    __shared__ int   sidx[TOPK_];

    const int b   = blockIdx.x;
    const int tid = threadIdx.x;

    const float* rrow = r + (size_t)b * N_;
    for (int i = tid; i < N_; i += 256) sr[i] = rrow[i];
    __syncthreads();

    for (int it = 0; it < TOPK_; ++it) {
        float bv = -1e30f; int bi = 0;
        for (int i = tid; i < N_; i += 256) {
            float v = sr[i];
            if (v > bv) { bv = v; bi = i; }
        }
        rv[tid] = bv; ri[tid] = bi;
        __syncthreads();
        for (int s = 128; s > 0; s >>= 1) {
            if (tid < s) {
                float v2 = rv[tid + s];
                if (v2 > rv[tid] || (v2 == rv[tid] && ri[tid + s] < ri[tid])) {
                    rv[tid] = v2; ri[tid] = ri[tid + s];
                }
            }
            __syncthreads();
        }
        if (tid == 0) {
            sidx[it] = ri[0];
            sr[ri[0]] = -1e30f;   // mask out the winner
        }
        __syncthreads();
    }

    if (tid < TOPK_) g_score[b * TOPK_ + tid] = 0.0f;

    // Gather the 16 selected rows (float4, coalesced)
    for (int lin = tid; lin < TOPK_ * (C_ / 4); lin += 256) {
        int k  = lin / (C_ / 4);
        int c4 = lin % (C_ / 4);
        float4 v = ((const float4*)(x + ((size_t)b * N_ + sidx[k]) * C_))[c4];
        ((float4*)(g_xg + (size_t)(b * TOPK_ + k) * C_))[c4] = v;
    }
}

// ---------------------------------------------------------------------------
// Kernel 2: pool GEMM  h = tanh(Xg @ W + b),  score += h . v   (fused)
// M=2048, N=768, K=768.  Tile 64x64, Kchunk=32, f32x2 micro-kernel 4x4/thread.
// ---------------------------------------------------------------------------
#define KB  32
#define SA  68     // As row stride (floats): 272B, 16B aligned, spreads banks
#define SBD 132    // value-duplicated B row stride (floats): 528B, 16B aligned

__global__ __launch_bounds__(256) void pool_kernel(
    const float* __restrict__ W, const float* __restrict__ Wb,
    const float* __restrict__ v)
{
    __shared__ float As[KB][SA];    // As[k][m] (transposed)
    __shared__ float Bd[KB][SBD];   // Bd[k][2n],Bd[k][2n+1] = W[k][n] duplicated
    __shared__ float bs[64];        // per-block partial scores per row

    const int tid = threadIdx.x;
    const int n0  = blockIdx.x * 64;
    const int m0  = blockIdx.y * 64;

    if (tid < 64) bs[tid] = 0.0f;

    unsigned long long acc[2][4];
    #pragma unroll
    for (int i = 0; i < 2; ++i)
        #pragma unroll
        for (int j = 0; j < 4; ++j) acc[i][j] = 0ull;

    const int rm = (tid & 15) * 4;   // 4 consecutive M rows
    const int cn = (tid >> 4) * 4;   // 4 consecutive N cols

    for (int k0 = 0; k0 < C_; k0 += KB) {
        #pragma unroll
        for (int it = 0; it < 2; ++it) {             // stage A (64x32, transposed)
            int lin = tid + it * 256;
            int m   = lin >> 3;
            int kv  = (lin & 7) * 4;
            float4 a = *(const float4*)(g_xg + (size_t)(m0 + m) * C_ + k0 + kv);
            As[kv + 0][m] = a.x; As[kv + 1][m] = a.y;
            As[kv + 2][m] = a.z; As[kv + 3][m] = a.w;
        }
        #pragma unroll
        for (int it = 0; it < 2; ++it) {             // stage B (32x64, duplicated)
            int lin = tid + it * 256;
            int k   = lin >> 4;
            int n4  = (lin & 15) * 4;
            float4 w = *(const float4*)(W + (size_t)(k0 + k) * H_ + n0 + n4);
            float* p = &Bd[k][2 * n4];
            p[0] = w.x; p[1] = w.x; p[2] = w.y; p[3] = w.y;
            p[4] = w.z; p[5] = w.z; p[6] = w.w; p[7] = w.w;
        }
        __syncthreads();
        #pragma unroll 8
        for (int kk = 0; kk < KB; ++kk) {
            ulonglong2 a01 = *(const ulonglong2*)&As[kk][rm];       // rows rm..rm+3
            ulonglong2 b01 = *(const ulonglong2*)&Bd[kk][2 * cn];   // (b0,b0),(b1,b1)
            ulonglong2 b23 = *(const ulonglong2*)&Bd[kk][2 * cn + 4];
            acc[0][0] = fma2(a01.x, b01.x, acc[0][0]);
            acc[0][1] = fma2(a01.x, b01.y, acc[0][1]);
            acc[0][2] = fma2(a01.x, b23.x, acc[0][2]);
            acc[0][3] = fma2(a01.x, b23.y, acc[0][3]);
            acc[1][0] = fma2(a01.y, b01.x, acc[1][0]);
            acc[1][1] = fma2(a01.y, b01.y, acc[1][1]);
            acc[1][2] = fma2(a01.y, b23.x, acc[1][2]);
            acc[1][3] = fma2(a01.y, b23.y, acc[1][3]);
        }
        __syncthreads();
    }

    // Epilogue: tanh + dot with v, reduce per-row
    float sp[4] = {0.f, 0.f, 0.f, 0.f};
    #pragma unroll
    for (int n = 0; n < 4; ++n) {
        int col  = n0 + cn + n;
        float wb = Wb[col];
        float vv = v[col];
        #pragma unroll
        for (int mp = 0; mp < 2; ++mp) {
            unsigned long long a = acc[mp][n];
            float lo = __uint_as_float((unsigned)(a & 0xffffffffull));
            float hi = __uint_as_float((unsigned)(a >> 32));
            sp[2 * mp + 0] += tanhf(lo + wb) * vv;
            sp[2 * mp + 1] += tanhf(hi + wb) * vv;
        }
    }
    #pragma unroll
    for (int j = 0; j < 4; ++j) atomicAdd(&bs[rm + j], sp[j]);
    __syncthreads();
    if (tid < 64) atomicAdd(&g_score[m0 + tid], bs[tid]);
}

// ---------------------------------------------------------------------------
// Kernel 3: softmax over 16 scores per batch + z = sum_k alpha_k * x_topk
// ---------------------------------------------------------------------------
__global__ __launch_bounds__(256) void finalize_kernel()
{
    const int b   = blockIdx.x;
    const int tid = threadIdx.x;
    __shared__ float sc[TOPK_];
    if (tid < TOPK_) sc[tid] = g_score[b * TOPK_ + tid];
    __syncthreads();

    float m = -1e30f;
    #pragma unroll
    for (int k = 0; k < TOPK_; ++k) m = fmaxf(m, sc[k]);
    float w[TOPK_]; float s = 0.0f;
    #pragma unroll
    for (int k = 0; k < TOPK_; ++k) { w[k] = expf(sc[k] - m); s += w[k]; }
    float inv = 1.0f / s;
    #pragma unroll
    for (int k = 0; k < TOPK_; ++k) w[k] *= inv;

    for (int c = tid; c < C_; c += 256) {
        float z = 0.0f;
        #pragma unroll
        for (int k = 0; k < TOPK_; ++k)
            z += w[k] * g_xg[(size_t)(b * TOPK_ + k) * C_ + c];
        g_z[(size_t)b * C_ + c] = z;
    }
}

// ---------------------------------------------------------------------------
// Kernel 4a: out = broadcast(fc_b)
// ---------------------------------------------------------------------------
__global__ __launch_bounds__(256) void init_out_kernel(
    float* __restrict__ out, const float* __restrict__ fcb)
{
    int i = blockIdx.x * 256 + threadIdx.x;
    if (i < B_ * NC_) out[i] = fcb[i % NC_];
}

// ---------------------------------------------------------------------------
// Kernel 4b: fc GEMM logits += z @ fc_w.  M=128, N=1000, K=768.
// Tile 64x64, K-split 6x128, atomicAdd into out.
// ---------------------------------------------------------------------------
__global__ __launch_bounds__(256) void fc_kernel(
    const float* __restrict__ fcw, float* __restrict__ out)
{
    __shared__ float As[KB][SA];
    __shared__ float Bd[KB][SBD];

    const int tid = threadIdx.x;
    const int n0  = blockIdx.x * 64;
    const int m0  = blockIdx.y * 64;
    const int kz0 = blockIdx.z * 128;

    unsigned long long acc[2][4];
    #pragma unroll
    for (int i = 0; i < 2; ++i)
        #pragma unroll
        for (int j = 0; j < 4; ++j) acc[i][j] = 0ull;

    const int rm = (tid & 15) * 4;
    const int cn = (tid >> 4) * 4;

    for (int k0 = kz0; k0 < kz0 + 128; k0 += KB) {
        #pragma unroll
        for (int it = 0; it < 2; ++it) {
            int lin = tid + it * 256;
            int m   = lin >> 3;
            int kv  = (lin & 7) * 4;
            float4 a = *(const float4*)(g_z + (size_t)(m0 + m) * C_ + k0 + kv);
            As[kv + 0][m] = a.x; As[kv + 1][m] = a.y;
            As[kv + 2][m] = a.z; As[kv + 3][m] = a.w;
        }
        #pragma unroll
        for (int it = 0; it < 2; ++it) {
            int lin = tid + it * 256;
            int k   = lin >> 4;
            int n4  = (lin & 15) * 4;
            int col = n0 + n4;
            float4 w = (col < NC_)
                ? *(const float4*)(fcw + (size_t)(k0 + k) * NC_ + col)
                : make_float4(0.f, 0.f, 0.f, 0.f);
            float* p = &Bd[k][2 * n4];
            p[0] = w.x; p[1] = w.x; p[2] = w.y; p[3] = w.y;
            p[4] = w.z; p[5] = w.z; p[6] = w.w; p[7] = w.w;
        }
        __syncthreads();
        #pragma unroll 8
        for (int kk = 0; kk < KB; ++kk) {
            ulonglong2 a01 = *(const ulonglong2*)&As[kk][rm];
            ulonglong2 b01 = *(const ulonglong2*)&Bd[kk][2 * cn];
            ulonglong2 b23 = *(const ulonglong2*)&Bd[kk][2 * cn + 4];
            acc[0][0] = fma2(a01.x, b01.x, acc[0][0]);
            acc[0][1] = fma2(a01.x, b01.y, acc[0][1]);
            acc[0][2] = fma2(a01.x, b23.x, acc[0][2]);
            acc[0][3] = fma2(a01.x, b23.y, acc[0][3]);
            acc[1][0] = fma2(a01.y, b01.x, acc[1][0]);
            acc[1][1] = fma2(a01.y, b01.y, acc[1][1]);
            acc[1][2] = fma2(a01.y, b23.x, acc[1][2]);
            acc[1][3] = fma2(a01.y, b23.y, acc[1][3]);
        }
        __syncthreads();
    }

    #pragma unroll
    for (int n = 0; n < 4; ++n) {
        int col = n0 + cn + n;
        if (col < NC_) {
            #pragma unroll
            for (int mp = 0; mp < 2; ++mp) {
                unsigned long long a = acc[mp][n];
                float lo = __uint_as_float((unsigned)(a & 0xffffffffull));
                float hi = __uint_as_float((unsigned)(a >> 32));
                int row0 = m0 + rm + 2 * mp;
                atomicAdd(&out[(size_t)row0 * NC_ + col], lo);
                atomicAdd(&out[(size_t)(row0 + 1) * NC_ + col], hi);
            }
        }
    }
}

// ---------------------------------------------------------------------------
extern "C" void kernel_launch(void* const* d_in, const int* in_sizes, int n_in,
                              void* d_out, int out_size)
{
    const float* x   = (const float*)d_in[0];
    const float* r   = (const float*)d_in[1];
    const float* pWw = (const float*)d_in[2];
    const float* pWb = (const float*)d_in[3];
    const float* pvw = (const float*)d_in[4];
    // d_in[5] = pool_v_b: constant shift before softmax -> cancels, unused
    const float* fcw = (const float*)d_in[6];
    const float* fcb = (const float*)d_in[7];
    float* out = (float*)d_out;

    topk_gather_kernel<<<B_, 256>>>(x, r);
    pool_kernel<<<dim3(H_ / 64, M_ / 64), 256>>>(pWw, pWb, pvw);   // (12, 32)
    finalize_kernel<<<B_, 256>>>();
    init_out_kernel<<<(B_ * NC_ + 255) / 256, 256>>>(out, fcb);    // 500 blocks
    fc_kernel<<<dim3(16, 2, 6), 256>>>(fcw, out);
}